// round 1
// baseline (speedup 1.0000x reference)
#include <cuda_runtime.h>
#include <cstdint>

#define V_  45
#define H_  1500
#define H2_ 3000
#define G4_ 6000   // 4*H
#define SW_ 50
#define SD_ 10

// ---------------- persistent device scratch (no allocations allowed) ----------------
__device__ float g_EV[2 * V_ * G4_];      // [dir][v][row] = W_ih[:, :H] @ emb[v] + b_ih + b_hh
__device__ float g_WST[2 * SW_ * G4_];    // [dir][k][row] = W_ih[row][H + k]  (transposed stack cols)
__device__ float g_gate[2 * G4_];         // phase A output: EV[tok] + W_hh @ h
__device__ float g_h[H2_];
__device__ float g_c[H2_];
__device__ float g_stack[2][SD_ * SW_];   // ping-pong
__device__ float g_ctrl_raw[3];
__device__ float g_si_raw[SW_];
__device__ unsigned g_bar_arrive;
__device__ unsigned g_bar_gen;

// ---------------- software grid barrier (all CTAs resident: grid == #SMs, occupancy>=1) ----------------
__device__ __forceinline__ void grid_sync(unsigned nblocks) {
    __syncthreads();
    if (threadIdx.x == 0) {
        volatile unsigned* genp = (volatile unsigned*)&g_bar_gen;
        unsigned gen = *genp;
        __threadfence();                            // release: prior writes visible before arrive
        if (atomicAdd(&g_bar_arrive, 1u) == nblocks - 1u) {
            atomicExch(&g_bar_arrive, 0u);
            __threadfence();
            *genp = gen + 1u;
        } else {
            while (*genp == gen) { __nanosleep(32); }
            __threadfence();                        // acquire
        }
    }
    __syncthreads();
}

// ---------------- prep kernels ----------------
__global__ void prep_state(const float* __restrict__ h0, const float* __restrict__ c0,
                           const float* __restrict__ st0) {
    int i = blockIdx.x * blockDim.x + threadIdx.x;
    if (i < H2_) { g_h[i] = h0[i]; g_c[i] = c0[i]; }
    if (i < SD_ * SW_) g_stack[0][i] = st0[i];
    if (i == 0) { g_bar_arrive = 0u; g_bar_gen = 0u; }
}

__global__ void pack_wst(const float* __restrict__ Wih_f, const float* __restrict__ Wih_b) {
    int idx = blockIdx.x * blockDim.x + threadIdx.x;
    if (idx >= 2 * SW_ * G4_) return;
    int d = idx / (SW_ * G4_);
    int rem = idx - d * (SW_ * G4_);
    int k = rem / G4_;
    int r = rem - k * G4_;
    const float* W = d ? Wih_b : Wih_f;
    g_WST[idx] = W[(size_t)r * (H_ + SW_) + H_ + k];
}

// EV[dir][v][r] = sum_k W_ih[dir][r][k] * emb[v][k] + b_ih[r] + b_hh[r]
// GEMM 6000x45x1500 per dir. Block: 256 threads -> 64 rows x 48 cols tile, K-chunk 16.
__global__ void __launch_bounds__(256) prep_ev(
    const float* __restrict__ Wih_f, const float* __restrict__ Wih_b,
    const float* __restrict__ bih_f, const float* __restrict__ bhh_f,
    const float* __restrict__ bih_b, const float* __restrict__ bhh_b,
    const float* __restrict__ emb) {
    __shared__ float As[64][17];   // [row][k] padded
    __shared__ float Bs[16][49];   // [k][v]   padded
    const int dir = blockIdx.y;
    const float* Wih = dir ? Wih_b : Wih_f;
    const float* bih = dir ? bih_b : bih_f;
    const float* bhh = dir ? bhh_b : bhh_f;
    const int r0 = blockIdx.x * 64;
    const int tid = threadIdx.x;
    const int ty = tid >> 4;   // 0..15 -> rows ty*4 .. ty*4+3
    const int tx = tid & 15;   // cols tx*3 .. tx*3+2
    float acc[4][3] = {};
    for (int k0 = 0; k0 < H_; k0 += 16) {
        #pragma unroll
        for (int j = 0; j < 4; ++j) {
            int li = tid + j * 256;
            int row = li >> 4, kk = li & 15;
            int gr = r0 + row, gk = k0 + kk;
            As[row][kk] = (gr < G4_ && gk < H_) ? Wih[(size_t)gr * (H_ + SW_) + gk] : 0.f;
        }
        #pragma unroll
        for (int j = 0; j < 3; ++j) {
            int li = tid + j * 256;
            int v = li >> 4, kk = li & 15;
            int gk = k0 + kk;
            Bs[kk][v] = (v < V_ && gk < H_) ? emb[(size_t)v * H_ + gk] : 0.f;
        }
        __syncthreads();
        #pragma unroll
        for (int kk = 0; kk < 16; ++kk) {
            float a0 = As[ty * 4 + 0][kk], a1 = As[ty * 4 + 1][kk];
            float a2 = As[ty * 4 + 2][kk], a3 = As[ty * 4 + 3][kk];
            float b0 = Bs[kk][tx * 3 + 0], b1 = Bs[kk][tx * 3 + 1], b2 = Bs[kk][tx * 3 + 2];
            acc[0][0] = fmaf(a0, b0, acc[0][0]); acc[0][1] = fmaf(a0, b1, acc[0][1]); acc[0][2] = fmaf(a0, b2, acc[0][2]);
            acc[1][0] = fmaf(a1, b0, acc[1][0]); acc[1][1] = fmaf(a1, b1, acc[1][1]); acc[1][2] = fmaf(a1, b2, acc[1][2]);
            acc[2][0] = fmaf(a2, b0, acc[2][0]); acc[2][1] = fmaf(a2, b1, acc[2][1]); acc[2][2] = fmaf(a2, b2, acc[2][2]);
            acc[3][0] = fmaf(a3, b0, acc[3][0]); acc[3][1] = fmaf(a3, b1, acc[3][1]); acc[3][2] = fmaf(a3, b2, acc[3][2]);
        }
        __syncthreads();
    }
    #pragma unroll
    for (int i = 0; i < 4; ++i) {
        int r = r0 + ty * 4 + i;
        if (r >= G4_) continue;
        float bb = bih[r] + bhh[r];
        #pragma unroll
        for (int j = 0; j < 3; ++j) {
            int v = tx * 3 + j;
            if (v < V_) g_EV[((size_t)(dir * V_ + v)) * G4_ + r] = acc[i][j] + bb;
        }
    }
}

// ---------------- persistent main kernel: all T steps, software grid sync ----------------
__global__ void __launch_bounds__(512, 1) rnn_main(
    const int* __restrict__ tokens,
    const float* __restrict__ Whh_f, const float* __restrict__ Whh_b,
    const float* __restrict__ Wctrl, const float* __restrict__ bctrl,
    const float* __restrict__ Wsi,   const float* __restrict__ bsi,
    const float* __restrict__ Wdec,  const float* __restrict__ bdec,
    float* __restrict__ out, int T) {
    __shared__ float sh_h[H2_];
    __shared__ float s_stop[SW_];
    __shared__ float s_si[SW_];

    const int tid  = threadIdx.x;
    const int lane = tid & 31;
    const int warp = tid >> 5;
    const int nwarps_blk = blockDim.x >> 5;
    const int gwarp = blockIdx.x * nwarps_blk + warp;
    const int NW = gridDim.x * nwarps_blk;
    // phase-B unit mapping: warp 0 of each block handles 32 contiguous hidden units -> spread over SMs
    const int uwarp = warp * gridDim.x + blockIdx.x;
    const int unit = uwarp * 32 + lane;

    const int NGATE = 2 * G4_;          // 12000 big rows (len-1500 dots)
    const int NTASK = NGATE + 3 + SW_ + V_;  // + ctrl + si + logits (len-3000 dots)

    for (int t = 0; t <= T; ++t) {
        // ---- phase A: everything that depends only on previous state ----
        for (int i = tid; i < H2_; i += blockDim.x) sh_h[i] = __ldcg(&g_h[i]);  // cross-SM -> bypass L1
        __syncthreads();
        const int tok = (t < T) ? tokens[t] : 0;

        for (int task = gwarp; task < NTASK; task += NW) {
            if (task < NGATE) {
                if (t >= T) continue;
                const int dir = (task >= G4_);
                const int r = task - dir * G4_;
                const float* Wrow = (dir ? Whh_b : Whh_f) + (size_t)r * H_;
                const float4* w4 = reinterpret_cast<const float4*>(Wrow);
                const float4* h4 = reinterpret_cast<const float4*>(sh_h + dir * H_);
                float acc = 0.f;
                #pragma unroll 4
                for (int i = lane; i < H_ / 4; i += 32) {
                    float4 a = w4[i]; float4 b = h4[i];
                    acc = fmaf(a.x, b.x, acc); acc = fmaf(a.y, b.y, acc);
                    acc = fmaf(a.z, b.z, acc); acc = fmaf(a.w, b.w, acc);
                }
                #pragma unroll
                for (int o = 16; o; o >>= 1) acc += __shfl_down_sync(0xffffffffu, acc, o);
                if (lane == 0)
                    g_gate[task] = acc + g_EV[((size_t)(dir * V_ + tok)) * G4_ + r];
            } else {
                const int id = task - NGATE;
                const float* row; float bias; float* dst; bool doit = true;
                if (id < 3) {                       // ctrl pre-softmax
                    if (t >= T) doit = false;
                    row = Wctrl + (size_t)id * H2_; bias = bctrl[id]; dst = &g_ctrl_raw[id];
                } else if (id < 3 + SW_) {          // si pre-tanh
                    if (t >= T) doit = false;
                    int k = id - 3;
                    row = Wsi + (size_t)k * H2_; bias = bsi[k]; dst = &g_si_raw[k];
                } else {                            // logits of previous step (uses current h)
                    int v = id - 3 - SW_;
                    if (t < 1) doit = false;
                    row = Wdec + (size_t)v * H2_; bias = bdec[v]; dst = out + (size_t)(t - 1) * V_ + v;
                }
                if (doit) {
                    const float4* w4 = reinterpret_cast<const float4*>(row);
                    const float4* h4 = reinterpret_cast<const float4*>(sh_h);
                    float acc = 0.f;
                    #pragma unroll 4
                    for (int i = lane; i < H2_ / 4; i += 32) {
                        float4 a = w4[i]; float4 b = h4[i];
                        acc = fmaf(a.x, b.x, acc); acc = fmaf(a.y, b.y, acc);
                        acc = fmaf(a.z, b.z, acc); acc = fmaf(a.w, b.w, acc);
                    }
                    #pragma unroll
                    for (int o = 16; o; o >>= 1) acc += __shfl_down_sync(0xffffffffu, acc, o);
                    if (lane == 0) *dst = acc + bias;
                }
            }
        }
        grid_sync(gridDim.x);
        if (t >= T) break;

        // ---- phase B: softmax/stack/gates/state update ----
        const float* stOld = g_stack[t & 1];
        float* stNew = g_stack[(t + 1) & 1];
        const float c0r = __ldcg(&g_ctrl_raw[0]);
        const float c1r = __ldcg(&g_ctrl_raw[1]);
        const float c2r = __ldcg(&g_ctrl_raw[2]);
        const float m = fmaxf(c0r, fmaxf(c1r, c2r));
        const float e0 = __expf(c0r - m), e1 = __expf(c1r - m), e2 = __expf(c2r - m);
        const float inv = 1.f / (e0 + e1 + e2);
        const float c0 = e0 * inv, c1 = e1 * inv, c2 = e2 * inv;   // push, pop, no-op

        if (tid < SW_) {
            float sv = tanhf(__ldcg(&g_si_raw[tid]));
            s_si[tid] = sv;
            s_stop[tid] = c2 * __ldcg(&stOld[tid]) + c0 * sv + c1 * __ldcg(&stOld[SW_ + tid]);
        }
        __syncthreads();

        if (unit < H2_) {
            const int d = (unit >= H_);
            const int i = unit - d * H_;
            const float* ws = g_WST + (size_t)d * SW_ * G4_ + i;
            float sp0 = 0.f, sp1 = 0.f, sp2 = 0.f, sp3 = 0.f;
            #pragma unroll
            for (int k = 0; k < SW_; ++k) {
                const float s = s_stop[k];
                const float* wk = ws + (size_t)k * G4_;
                sp0 = fmaf(wk[0],        s, sp0);
                sp1 = fmaf(wk[H_],       s, sp1);
                sp2 = fmaf(wk[2 * H_],   s, sp2);
                sp3 = fmaf(wk[3 * H_],   s, sp3);
            }
            const float* gg = g_gate + (size_t)d * G4_ + i;
            const float gi = __ldcg(&gg[0])       + sp0;
            const float gf = __ldcg(&gg[H_])      + sp1;
            const float gG = __ldcg(&gg[2 * H_])  + sp2;
            const float go = __ldcg(&gg[3 * H_])  + sp3;
            const float is = 1.f / (1.f + __expf(-gi));
            const float fs = 1.f / (1.f + __expf(-gf));
            const float gt = tanhf(gG);
            const float os = 1.f / (1.f + __expf(-go));
            const float cc = fs * g_c[unit] + is * gt;   // g_c is thread-private across steps
            g_c[unit] = cc;
            g_h[unit] = os * tanhf(cc);
        }
        if (blockIdx.x == 0 && tid < SD_ * SW_) {
            const int dd = tid / SW_, k = tid - dd * SW_;
            const float up = (dd == 0) ? s_si[k] : __ldcg(&stOld[(dd - 1) * SW_ + k]);
            const float dn = (dd < SD_ - 1) ? __ldcg(&stOld[(dd + 1) * SW_ + k]) : 0.f;
            stNew[dd * SW_ + k] = c2 * __ldcg(&stOld[dd * SW_ + k]) + c0 * up + c1 * dn;
        }
        grid_sync(gridDim.x);
    }
}

// ---------------- launch ----------------
extern "C" void kernel_launch(void* const* d_in, const int* in_sizes, int n_in,
                              void* d_out, int out_size) {
    const int*   tokens  = (const int*)  d_in[0];
    const float* hidden0 = (const float*)d_in[1];
    const float* cell0   = (const float*)d_in[2];
    const float* stack0  = (const float*)d_in[3];
    const float* emb     = (const float*)d_in[4];
    const float* Wctrl   = (const float*)d_in[5];
    const float* bctrl   = (const float*)d_in[6];
    const float* Wsi     = (const float*)d_in[7];
    const float* bsi     = (const float*)d_in[8];
    const float* Wih_f   = (const float*)d_in[9];
    const float* Whh_f   = (const float*)d_in[10];
    const float* bih_f   = (const float*)d_in[11];
    const float* bhh_f   = (const float*)d_in[12];
    const float* Wih_b   = (const float*)d_in[13];
    const float* Whh_b   = (const float*)d_in[14];
    const float* bih_b   = (const float*)d_in[15];
    const float* bhh_b   = (const float*)d_in[16];
    const float* Wdec    = (const float*)d_in[17];
    const float* bdec    = (const float*)d_in[18];
    float* out = (float*)d_out;
    const int T = in_sizes[0];

    int dev = 0;
    cudaGetDevice(&dev);
    int nsm = 0;
    cudaDeviceGetAttribute(&nsm, cudaDevAttrMultiProcessorCount, dev);
    if (nsm <= 0) nsm = 148;

    prep_state<<<(H2_ + 255) / 256, 256>>>(hidden0, cell0, stack0);
    pack_wst<<<(2 * SW_ * G4_ + 255) / 256, 256>>>(Wih_f, Wih_b);
    dim3 gev((G4_ + 63) / 64, 2);
    prep_ev<<<gev, 256>>>(Wih_f, Wih_b, bih_f, bhh_f, bih_b, bhh_b, emb);
    rnn_main<<<nsm, 512>>>(tokens, Whh_f, Whh_b, Wctrl, bctrl, Wsi, bsi,
                           Wdec, bdec, out, T);
}

// round 2
// speedup vs baseline: 1.1844x; 1.1844x over previous
#include <cuda_runtime.h>
#include <cuda_fp16.h>
#include <cstdint>

#define V_   45
#define H_   1500
#define H2_  3000
#define G4_  6000   // 4*H
#define SW_  50
#define SD_  10
#define HP_  1536   // H padded to 8*32*6
#define H2P_ 3072   // 2H padded (two 1536 halves: [h_f | pad | h_b | pad])
#define NSMALL_ 98  // 3 ctrl + 50 si + 45 dec

// ---------------- persistent device scratch ----------------
__device__ float g_EV[2 * V_ * G4_];                 // [dir][v][row] fp32
__device__ float g_WST[2 * SW_ * G4_];               // [dir][k][row] fp32
__device__ __align__(16) __half g_Whh[2 * G4_ * HP_];    // padded fp16 W_hh rows
__device__ __align__(16) __half g_Wsm[NSMALL_ * H2P_];   // padded fp16 small rows (ctrl|si|dec)
__device__ float g_gate[2 * G4_];
__device__ float g_h[H2P_];                          // padded hidden (holes = 0)
__device__ float g_c[H2_];
__device__ float g_stack[2][SD_ * SW_];
__device__ float g_ctrl_raw[3];
__device__ float g_si_raw[SW_];
__device__ volatile unsigned g_arr[512];
__device__ volatile unsigned g_gen;

// ---------------- distributed-flag grid barrier ----------------
__device__ __forceinline__ void gsync(unsigned gen, int nb) {
    __syncthreads();
    const int tid = threadIdx.x;
    if (tid == 0) {
        __threadfence();                 // release prior global writes
        g_arr[blockIdx.x] = gen;         // volatile store (L2)
    }
    if (blockIdx.x == 0) {
        if (tid < nb) {
            while (g_arr[tid] < gen) { }
        }
        __syncthreads();
        if (tid == 0) g_gen = gen;
    } else {
        if (tid == 0) {
            while (g_gen < gen) { }
        }
        __syncthreads();
    }
    __threadfence();                     // acquire-ish ordering for subsequent L2 reads
    __syncthreads();
}

// ---------------- prep kernels ----------------
__global__ void prep_state(const float* __restrict__ h0, const float* __restrict__ c0,
                           const float* __restrict__ st0) {
    int i = blockIdx.x * blockDim.x + threadIdx.x;
    if (i < H2P_) {
        int d = i >= HP_;
        int j = i - d * HP_;
        g_h[i] = (j < H_) ? h0[d * H_ + j] : 0.f;
    }
    if (i < H2_) g_c[i] = c0[i];
    if (i < SD_ * SW_) g_stack[0][i] = st0[i];
    if (i < 512) g_arr[i] = 0u;
    if (i == 0) g_gen = 0u;
}

__global__ void conv_whh(const float* __restrict__ Wf, const float* __restrict__ Wb) {
    int idx = blockIdx.x * blockDim.x + threadIdx.x;
    if (idx >= 2 * G4_ * HP_) return;
    int d = idx / (G4_ * HP_);
    int rem = idx - d * (G4_ * HP_);
    int r = rem / HP_;
    int k = rem - r * HP_;
    const float* W = d ? Wb : Wf;
    float v = (k < H_) ? W[(size_t)r * H_ + k] : 0.f;
    g_Whh[idx] = __float2half(v);
}

__global__ void conv_small(const float* __restrict__ Wc, const float* __restrict__ Ws,
                           const float* __restrict__ Wd) {
    int idx = blockIdx.x * blockDim.x + threadIdx.x;
    if (idx >= NSMALL_ * H2P_) return;
    int row = idx / H2P_;
    int j = idx - row * H2P_;
    int d = j >= HP_;
    int jj = j - d * HP_;
    float v = 0.f;
    if (jj < H_) {
        int c = d * H_ + jj;             // source col in [0, 3000)
        const float* src;
        int r;
        if (row < 3)       { src = Wc; r = row; }
        else if (row < 53) { src = Ws; r = row - 3; }
        else               { src = Wd; r = row - 53; }
        v = src[(size_t)r * H2_ + c];
    }
    g_Wsm[idx] = __float2half(v);
}

__global__ void pack_wst(const float* __restrict__ Wih_f, const float* __restrict__ Wih_b) {
    int idx = blockIdx.x * blockDim.x + threadIdx.x;
    if (idx >= 2 * SW_ * G4_) return;
    int d = idx / (SW_ * G4_);
    int rem = idx - d * (SW_ * G4_);
    int k = rem / G4_;
    int r = rem - k * G4_;
    const float* W = d ? Wih_b : Wih_f;
    g_WST[idx] = W[(size_t)r * (H_ + SW_) + H_ + k];
}

// EV[dir][v][r] = W_ih[:, :H] @ emb[v] + b_ih + b_hh   (6000x45x1500 per dir)
__global__ void __launch_bounds__(256) prep_ev(
    const float* __restrict__ Wih_f, const float* __restrict__ Wih_b,
    const float* __restrict__ bih_f, const float* __restrict__ bhh_f,
    const float* __restrict__ bih_b, const float* __restrict__ bhh_b,
    const float* __restrict__ emb) {
    __shared__ float As[64][17];
    __shared__ float Bs[16][49];
    const int dir = blockIdx.y;
    const float* Wih = dir ? Wih_b : Wih_f;
    const float* bih = dir ? bih_b : bih_f;
    const float* bhh = dir ? bhh_b : bhh_f;
    const int r0 = blockIdx.x * 64;
    const int tid = threadIdx.x;
    const int ty = tid >> 4;
    const int tx = tid & 15;
    float acc[4][3] = {};
    for (int k0 = 0; k0 < H_; k0 += 16) {
        #pragma unroll
        for (int j = 0; j < 4; ++j) {
            int li = tid + j * 256;
            int row = li >> 4, kk = li & 15;
            int gr = r0 + row, gk = k0 + kk;
            As[row][kk] = (gr < G4_ && gk < H_) ? Wih[(size_t)gr * (H_ + SW_) + gk] : 0.f;
        }
        #pragma unroll
        for (int j = 0; j < 3; ++j) {
            int li = tid + j * 256;
            int v = li >> 4, kk = li & 15;
            int gk = k0 + kk;
            Bs[kk][v] = (v < V_ && gk < H_) ? emb[(size_t)v * H_ + gk] : 0.f;
        }
        __syncthreads();
        #pragma unroll
        for (int kk = 0; kk < 16; ++kk) {
            float a0 = As[ty * 4 + 0][kk], a1 = As[ty * 4 + 1][kk];
            float a2 = As[ty * 4 + 2][kk], a3 = As[ty * 4 + 3][kk];
            float b0 = Bs[kk][tx * 3 + 0], b1 = Bs[kk][tx * 3 + 1], b2 = Bs[kk][tx * 3 + 2];
            acc[0][0] = fmaf(a0, b0, acc[0][0]); acc[0][1] = fmaf(a0, b1, acc[0][1]); acc[0][2] = fmaf(a0, b2, acc[0][2]);
            acc[1][0] = fmaf(a1, b0, acc[1][0]); acc[1][1] = fmaf(a1, b1, acc[1][1]); acc[1][2] = fmaf(a1, b2, acc[1][2]);
            acc[2][0] = fmaf(a2, b0, acc[2][0]); acc[2][1] = fmaf(a2, b1, acc[2][1]); acc[2][2] = fmaf(a2, b2, acc[2][2]);
            acc[3][0] = fmaf(a3, b0, acc[3][0]); acc[3][1] = fmaf(a3, b1, acc[3][1]); acc[3][2] = fmaf(a3, b2, acc[3][2]);
        }
        __syncthreads();
    }
    #pragma unroll
    for (int i = 0; i < 4; ++i) {
        int r = r0 + ty * 4 + i;
        if (r >= G4_) continue;
        float bb = bih[r] + bhh[r];
        #pragma unroll
        for (int j = 0; j < 3; ++j) {
            int v = tx * 3 + j;
            if (v < V_) g_EV[((size_t)(dir * V_ + v)) * G4_ + r] = acc[i][j] + bb;
        }
    }
}

// fp16x8 dot helper: u holds 8 halves; hA/hB the matching 8 floats
__device__ __forceinline__ void fma8(float& acc, uint4 u, float4 hA, float4 hB) {
    float2 f0 = __half22float2(*reinterpret_cast<__half2*>(&u.x));
    float2 f1 = __half22float2(*reinterpret_cast<__half2*>(&u.y));
    float2 f2 = __half22float2(*reinterpret_cast<__half2*>(&u.z));
    float2 f3 = __half22float2(*reinterpret_cast<__half2*>(&u.w));
    acc = fmaf(f0.x, hA.x, acc); acc = fmaf(f0.y, hA.y, acc);
    acc = fmaf(f1.x, hA.z, acc); acc = fmaf(f1.y, hA.w, acc);
    acc = fmaf(f2.x, hB.x, acc); acc = fmaf(f2.y, hB.y, acc);
    acc = fmaf(f3.x, hB.z, acc); acc = fmaf(f3.y, hB.w, acc);
}

// ---------------- persistent main kernel ----------------
__global__ void __launch_bounds__(512, 1) rnn_main(
    const int* __restrict__ tokens,
    const float* __restrict__ bctrl, const float* __restrict__ bsi,
    const float* __restrict__ bdec,
    float* __restrict__ out, int T) {
    __shared__ __align__(16) float sh_h[H2P_];
    __shared__ float s_stop[SW_];
    __shared__ float s_si[SW_];

    const int tid  = threadIdx.x;
    const int lane = tid & 31;
    const int warp = tid >> 5;
    const int nwarps_blk = blockDim.x >> 5;
    const int gwarp = blockIdx.x * nwarps_blk + warp;
    const int NW = gridDim.x * nwarps_blk;
    const int uwarp = warp * gridDim.x + blockIdx.x;
    const int unit = uwarp * 32 + lane;

    const int NPAIR = G4_;                  // 6000 pair-tasks (2 gate rows each)
    const int NTASK = NPAIR + NSMALL_;

    unsigned gen = 1;

    for (int t = 0; t <= T; ++t) {
        // ---- phase A ----
        for (int i = tid; i < H2P_; i += blockDim.x) sh_h[i] = __ldcg(&g_h[i]);
        __syncthreads();
        const int tok = (t < T) ? tokens[t] : 0;

        for (int task = gwarp; task < NTASK; task += NW) {
            if (task < NPAIR) {
                if (t >= T) continue;
                const int dir = (task >= NPAIR / 2);
                const int r = (task - dir * (NPAIR / 2)) * 2;   // even row in [0,6000)
                const uint4* W0 = reinterpret_cast<const uint4*>(g_Whh + ((size_t)(dir * G4_ + r)) * HP_);
                const uint4* W1 = W0 + HP_ / 8;
                const float* hb = sh_h + dir * HP_;
                float a0 = 0.f, a1 = 0.f;
                #pragma unroll
                for (int it = 0; it < 6; ++it) {
                    const int o = lane + it * 32;
                    uint4 u0 = W0[o];
                    uint4 u1 = W1[o];
                    float4 hA = *reinterpret_cast<const float4*>(hb + o * 8);
                    float4 hB = *reinterpret_cast<const float4*>(hb + o * 8 + 4);
                    fma8(a0, u0, hA, hB);
                    fma8(a1, u1, hA, hB);
                }
                #pragma unroll
                for (int o = 16; o; o >>= 1) {
                    a0 += __shfl_xor_sync(0xffffffffu, a0, o);
                    a1 += __shfl_xor_sync(0xffffffffu, a1, o);
                }
                if (lane == 0) {
                    const float2 ev = *reinterpret_cast<const float2*>(
                        &g_EV[((size_t)(dir * V_ + tok)) * G4_ + r]);
                    g_gate[dir * G4_ + r]     = a0 + ev.x;
                    g_gate[dir * G4_ + r + 1] = a1 + ev.y;
                }
            } else {
                const int id = task - NPAIR;            // 0..97
                float bias; float* dst; bool doit = true;
                if (id < 3) {
                    if (t >= T) doit = false;
                    bias = bctrl[id]; dst = &g_ctrl_raw[id];
                } else if (id < 53) {
                    if (t >= T) doit = false;
                    bias = bsi[id - 3]; dst = &g_si_raw[id - 3];
                } else {
                    if (t < 1) doit = false;
                    bias = bdec[id - 53]; dst = out + (size_t)(t - 1) * V_ + (id - 53);
                }
                if (doit) {
                    const uint4* W = reinterpret_cast<const uint4*>(g_Wsm + (size_t)id * H2P_);
                    float acc = 0.f;
                    #pragma unroll
                    for (int it = 0; it < 12; ++it) {
                        const int o = lane + it * 32;
                        uint4 u = W[o];
                        float4 hA = *reinterpret_cast<const float4*>(sh_h + o * 8);
                        float4 hB = *reinterpret_cast<const float4*>(sh_h + o * 8 + 4);
                        fma8(acc, u, hA, hB);
                    }
                    #pragma unroll
                    for (int o = 16; o; o >>= 1) acc += __shfl_xor_sync(0xffffffffu, acc, o);
                    if (lane == 0) *dst = acc + bias;
                }
            }
        }
        gsync(gen++, gridDim.x);
        if (t >= T) break;

        // ---- phase B ----
        const float* stOld = g_stack[t & 1];
        float* stNew = g_stack[(t + 1) & 1];
        const float c0r = __ldcg(&g_ctrl_raw[0]);
        const float c1r = __ldcg(&g_ctrl_raw[1]);
        const float c2r = __ldcg(&g_ctrl_raw[2]);
        const float m = fmaxf(c0r, fmaxf(c1r, c2r));
        const float e0 = __expf(c0r - m), e1 = __expf(c1r - m), e2 = __expf(c2r - m);
        const float inv = 1.f / (e0 + e1 + e2);
        const float c0 = e0 * inv, c1 = e1 * inv, c2 = e2 * inv;

        if (tid < SW_) {
            float sv = tanhf(__ldcg(&g_si_raw[tid]));
            s_si[tid] = sv;
            s_stop[tid] = c2 * __ldcg(&stOld[tid]) + c0 * sv + c1 * __ldcg(&stOld[SW_ + tid]);
        }
        __syncthreads();

        if (unit < H2_) {
            const int d = (unit >= H_);
            const int i = unit - d * H_;
            const float* ws = g_WST + (size_t)d * SW_ * G4_ + i;
            float sp0 = 0.f, sp1 = 0.f, sp2 = 0.f, sp3 = 0.f;
            #pragma unroll
            for (int k = 0; k < SW_; ++k) {
                const float s = s_stop[k];
                const float* wk = ws + (size_t)k * G4_;
                sp0 = fmaf(wk[0],      s, sp0);
                sp1 = fmaf(wk[H_],     s, sp1);
                sp2 = fmaf(wk[2 * H_], s, sp2);
                sp3 = fmaf(wk[3 * H_], s, sp3);
            }
            const float* gg = g_gate + (size_t)d * G4_ + i;
            const float gi = __ldcg(&gg[0])      + sp0;
            const float gf = __ldcg(&gg[H_])     + sp1;
            const float gG = __ldcg(&gg[2 * H_]) + sp2;
            const float go = __ldcg(&gg[3 * H_]) + sp3;
            const float is = 1.f / (1.f + __expf(-gi));
            const float fs = 1.f / (1.f + __expf(-gf));
            const float gt = tanhf(gG);
            const float os = 1.f / (1.f + __expf(-go));
            const float cc = fs * g_c[unit] + is * gt;
            g_c[unit] = cc;
            g_h[d * HP_ + i] = os * tanhf(cc);
        }
        if (blockIdx.x == 0 && tid < SD_ * SW_) {
            const int dd = tid / SW_, k = tid - dd * SW_;
            const float up = (dd == 0) ? s_si[k] : __ldcg(&stOld[(dd - 1) * SW_ + k]);
            const float dn = (dd < SD_ - 1) ? __ldcg(&stOld[(dd + 1) * SW_ + k]) : 0.f;
            stNew[dd * SW_ + k] = c2 * __ldcg(&stOld[dd * SW_ + k]) + c0 * up + c1 * dn;
        }
        gsync(gen++, gridDim.x);
    }
}

// ---------------- launch ----------------
extern "C" void kernel_launch(void* const* d_in, const int* in_sizes, int n_in,
                              void* d_out, int out_size) {
    const int*   tokens  = (const int*)  d_in[0];
    const float* hidden0 = (const float*)d_in[1];
    const float* cell0   = (const float*)d_in[2];
    const float* stack0  = (const float*)d_in[3];
    const float* emb     = (const float*)d_in[4];
    const float* Wctrl   = (const float*)d_in[5];
    const float* bctrl   = (const float*)d_in[6];
    const float* Wsi     = (const float*)d_in[7];
    const float* bsi     = (const float*)d_in[8];
    const float* Wih_f   = (const float*)d_in[9];
    const float* Whh_f   = (const float*)d_in[10];
    const float* bih_f   = (const float*)d_in[11];
    const float* bhh_f   = (const float*)d_in[12];
    const float* Wih_b   = (const float*)d_in[13];
    const float* Whh_b   = (const float*)d_in[14];
    const float* bih_b   = (const float*)d_in[15];
    const float* bhh_b   = (const float*)d_in[16];
    const float* Wdec    = (const float*)d_in[17];
    const float* bdec    = (const float*)d_in[18];
    float* out = (float*)d_out;
    const int T = in_sizes[0];

    int dev = 0;
    cudaGetDevice(&dev);
    int nsm = 0;
    cudaDeviceGetAttribute(&nsm, cudaDevAttrMultiProcessorCount, dev);
    if (nsm <= 0) nsm = 148;

    prep_state<<<(H2P_ + 255) / 256, 256>>>(hidden0, cell0, stack0);
    conv_whh<<<(2 * G4_ * HP_ + 255) / 256, 256>>>(Whh_f, Whh_b);
    conv_small<<<(NSMALL_ * H2P_ + 255) / 256, 256>>>(Wctrl, Wsi, Wdec);
    pack_wst<<<(2 * SW_ * G4_ + 255) / 256, 256>>>(Wih_f, Wih_b);
    dim3 gev((G4_ + 63) / 64, 2);
    prep_ev<<<gev, 256>>>(Wih_f, Wih_b, bih_f, bhh_f, bih_b, bhh_b, emb);
    rnn_main<<<nsm, 512>>>(tokens, bctrl, bsi, bdec, out, T);
}